// round 1
// baseline (speedup 1.0000x reference)
#include <cuda_runtime.h>
#include <cstdint>

// Problem constants
#define BATCH 8
#define NHID 256
#define LEN 2048
#define NHEAD 8
#define HDIM 64
#define DQKV 512            // NHEAD * HDIM
#define DOUT 2048           // output channels of Wo
#define MTOT (BATCH * LEN)  // 16384

// GEMM tiling
#define BM 128
#define BN 128
#define BK 16
#define PITCH 132           // smem row pitch (floats), 132*4 % 16 == 0

// Scratch (allocation-free: __device__ globals)
__device__ float g_qkv[(size_t)MTOT * 1536];  // [m][0:512]=q, [512:1024]=k, [1024:1536]=v
__device__ float g_att[(size_t)MTOT * DQKV];

// ---------------- packed f32x2 helpers (sm_103a FFMA2) ----------------
__device__ __forceinline__ unsigned long long pack2(float x, float y) {
    unsigned long long r;
    asm("mov.b64 %0, {%1, %2};" : "=l"(r)
        : "r"(__float_as_uint(x)), "r"(__float_as_uint(y)));
    return r;
}
__device__ __forceinline__ void unpack2(unsigned long long v, float& x, float& y) {
    unsigned a, b;
    asm("mov.b64 {%0, %1}, %2;" : "=r"(a), "=r"(b) : "l"(v));
    x = __uint_as_float(a);
    y = __uint_as_float(b);
}
__device__ __forceinline__ void fma2(unsigned long long& d,
                                     unsigned long long a, unsigned long long b) {
    asm("fma.rn.f32x2 %0, %1, %2, %3;" : "=l"(d) : "l"(a), "l"(b), "l"(d));
}

// ---------------- Kernel 1: QKV projection ----------------
// A[m][k] = x[b][k][l]  (x is [B, NHID, L, 1]; inner L contiguous)
// B = Wq/Wk/Wv [256, 512], C -> g_qkv[m][mat*512 + n]
__global__ __launch_bounds__(256) void qkv_gemm(
    const float* __restrict__ x,
    const float* __restrict__ Wq, const float* __restrict__ bq,
    const float* __restrict__ Wk, const float* __restrict__ bk,
    const float* __restrict__ Wv, const float* __restrict__ bv)
{
    __shared__ float As[BK * PITCH];
    __shared__ float Bs[BK * PITCH];

    const int m0 = blockIdx.x * BM;       // 0..16383, tiles never cross batch
    const int b  = m0 >> 11;              // / 2048
    const int l0 = m0 & (LEN - 1);
    const int nt = blockIdx.y;            // 0..11
    const int mat = nt >> 2;              // 0=q 1=k 2=v
    const int n0  = (nt & 3) * BN;

    const float* W    = (mat == 0) ? Wq : (mat == 1) ? Wk : Wv;
    const float* bias = (mat == 0) ? bq : (mat == 1) ? bk : bv;
    const float* xb   = x + (size_t)b * NHID * LEN + l0;  // x[b][k][l0+..]

    const int tid  = threadIdx.x;
    const int tx   = tid & 15, ty = tid >> 4;
    const int row0 = ty * 8, col0 = tx * 8;

    unsigned long long acc[8][4];
#pragma unroll
    for (int i = 0; i < 8; i++)
#pragma unroll
        for (int j = 0; j < 4; j++) acc[i][j] = 0ull;

    for (int k0 = 0; k0 < NHID; k0 += BK) {
        // A tile: 16(k) x 128(l); x rows are L-contiguous -> coalesced float4
#pragma unroll
        for (int it = 0; it < 2; it++) {
            int f  = tid + it * 256;          // 0..511
            int kk = f >> 5;                  // 0..15
            int li = (f & 31) << 2;           // 0..124
            float4 v = *(const float4*)(xb + (size_t)(k0 + kk) * LEN + li);
            *(float4*)&As[kk * PITCH + li] = v;
        }
        // B tile: W[k0+kk][n0+ni]
#pragma unroll
        for (int it = 0; it < 2; it++) {
            int f  = tid + it * 256;
            int kk = f >> 5;
            int ni = (f & 31) << 2;
            float4 v = *(const float4*)(W + (size_t)(k0 + kk) * DQKV + n0 + ni);
            *(float4*)&Bs[kk * PITCH + ni] = v;
        }
        __syncthreads();

#pragma unroll
        for (int k = 0; k < BK; k++) {
            float4 a0 = *(const float4*)&As[k * PITCH + row0];
            float4 a1 = *(const float4*)&As[k * PITCH + row0 + 4];
            float4 b0 = *(const float4*)&Bs[k * PITCH + col0];
            float4 b1 = *(const float4*)&Bs[k * PITCH + col0 + 4];
            unsigned long long bb0 = pack2(b0.x, b0.y);
            unsigned long long bb1 = pack2(b0.z, b0.w);
            unsigned long long bb2 = pack2(b1.x, b1.y);
            unsigned long long bb3 = pack2(b1.z, b1.w);
            float av[8] = {a0.x, a0.y, a0.z, a0.w, a1.x, a1.y, a1.z, a1.w};
#pragma unroll
            for (int i = 0; i < 8; i++) {
                unsigned long long aa = pack2(av[i], av[i]);
                fma2(acc[i][0], aa, bb0);
                fma2(acc[i][1], aa, bb1);
                fma2(acc[i][2], aa, bb2);
                fma2(acc[i][3], aa, bb3);
            }
        }
        __syncthreads();
    }

    float C[8][8];
#pragma unroll
    for (int i = 0; i < 8; i++)
#pragma unroll
        for (int jp = 0; jp < 4; jp++)
            unpack2(acc[i][jp], C[i][2 * jp], C[i][2 * jp + 1]);

    const float4 bia0 = *(const float4*)(bias + n0 + col0);
    const float4 bia1 = *(const float4*)(bias + n0 + col0 + 4);
    float* obase = g_qkv + (size_t)(m0 + row0) * 1536 + (size_t)mat * DQKV + n0 + col0;
#pragma unroll
    for (int i = 0; i < 8; i++) {
        float4 w0 = make_float4(C[i][0] + bia0.x, C[i][1] + bia0.y,
                                C[i][2] + bia0.z, C[i][3] + bia0.w);
        float4 w1 = make_float4(C[i][4] + bia1.x, C[i][5] + bia1.y,
                                C[i][6] + bia1.z, C[i][7] + bia1.w);
        *(float4*)(obase + (size_t)i * 1536)     = w0;
        *(float4*)(obase + (size_t)i * 1536 + 4) = w1;
    }
}

// ---------------- Kernel 2: window-3 attention ----------------
// One warp per (b, l, head). Zero-padded boundary => score contribution
// is exactly 0 (dot with zero k), included in softmax; v contribution zero.
__global__ __launch_bounds__(256) void attn_kernel()
{
    const int warp = threadIdx.x >> 5;
    const int lane = threadIdx.x & 31;
    const int wid  = blockIdx.x * 8 + warp;  // 0 .. 131071
    const int n = wid & 7;
    const int l = (wid >> 3) & (LEN - 1);
    const int b = wid >> 14;

    const size_t m = (size_t)b * LEN + l;
    const float2 qv = *(const float2*)(g_qkv + m * 1536 + n * HDIM + lane * 2);

    float  s[3];
    float2 vv[3];
#pragma unroll
    for (int w = 0; w < 3; w++) {
        int lw = l + w - 1;
        bool ok = (unsigned)lw < (unsigned)LEN;
        float2 kv = make_float2(0.f, 0.f);
        vv[w] = make_float2(0.f, 0.f);
        if (ok) {
            const float* base = g_qkv + ((size_t)b * LEN + lw) * 1536 + n * HDIM + lane * 2;
            kv    = *(const float2*)(base + 512);
            vv[w] = *(const float2*)(base + 1024);
        }
        float p = qv.x * kv.x + qv.y * kv.y;
        p += __shfl_xor_sync(0xffffffffu, p, 16);
        p += __shfl_xor_sync(0xffffffffu, p, 8);
        p += __shfl_xor_sync(0xffffffffu, p, 4);
        p += __shfl_xor_sync(0xffffffffu, p, 2);
        p += __shfl_xor_sync(0xffffffffu, p, 1);
        s[w] = p * 0.125f;  // 1/sqrt(64)
    }

    float mx = fmaxf(s[0], fmaxf(s[1], s[2]));
    float e0 = expf(s[0] - mx), e1 = expf(s[1] - mx), e2 = expf(s[2] - mx);
    float inv = 1.0f / (e0 + e1 + e2);
    float ax = (e0 * vv[0].x + e1 * vv[1].x + e2 * vv[2].x) * inv;
    float ay = (e0 * vv[0].y + e1 * vv[1].y + e2 * vv[2].y) * inv;
    *(float2*)(g_att + m * DQKV + n * HDIM + lane * 2) = make_float2(ax, ay);
}

// ---------------- Kernel 3: output projection + transposed write ----------------
// A = g_att [16384, 512] row-major, B = Wo [512, 2048]
// out[b][o][l] = (A @ Wo + bo), written as float4 along L (coalesced-ish)
__global__ __launch_bounds__(256) void out_gemm(
    const float* __restrict__ Wo, const float* __restrict__ bo,
    float* __restrict__ out)
{
    __shared__ float As[BK * PITCH];  // transposed: [k][m]
    __shared__ float Bs[BK * PITCH];

    const int m0 = blockIdx.x * BM;
    const int b  = m0 >> 11;
    const int l0 = m0 & (LEN - 1);
    const int n0 = blockIdx.y * BN;

    const int tid  = threadIdx.x;
    const int tx   = tid & 15, ty = tid >> 4;
    const int row0 = ty * 8, col0 = tx * 8;

    unsigned long long acc[8][4];
#pragma unroll
    for (int i = 0; i < 8; i++)
#pragma unroll
        for (int j = 0; j < 4; j++) acc[i][j] = 0ull;

    for (int k0 = 0; k0 < DQKV; k0 += BK) {
        // A tile transposed on store: read row-major float4, scatter to As[k][m]
#pragma unroll
        for (int it = 0; it < 2; it++) {
            int f  = tid + it * 256;         // 0..511
            int r  = f >> 2;                 // 0..127  (m within tile)
            int c4 = (f & 3) << 2;           // 0,4,8,12 (k within tile)
            float4 v = *(const float4*)(g_att + (size_t)(m0 + r) * DQKV + k0 + c4);
            As[(c4 + 0) * PITCH + r] = v.x;
            As[(c4 + 1) * PITCH + r] = v.y;
            As[(c4 + 2) * PITCH + r] = v.z;
            As[(c4 + 3) * PITCH + r] = v.w;
        }
        // B tile: Wo[k0+kk][n0+ni], row stride 2048
#pragma unroll
        for (int it = 0; it < 2; it++) {
            int f  = tid + it * 256;
            int kk = f >> 5;
            int ni = (f & 31) << 2;
            float4 v = *(const float4*)(Wo + (size_t)(k0 + kk) * DOUT + n0 + ni);
            *(float4*)&Bs[kk * PITCH + ni] = v;
        }
        __syncthreads();

#pragma unroll
        for (int k = 0; k < BK; k++) {
            float4 a0 = *(const float4*)&As[k * PITCH + row0];
            float4 a1 = *(const float4*)&As[k * PITCH + row0 + 4];
            float4 b0 = *(const float4*)&Bs[k * PITCH + col0];
            float4 b1 = *(const float4*)&Bs[k * PITCH + col0 + 4];
            unsigned long long bb0 = pack2(b0.x, b0.y);
            unsigned long long bb1 = pack2(b0.z, b0.w);
            unsigned long long bb2 = pack2(b1.x, b1.y);
            unsigned long long bb3 = pack2(b1.z, b1.w);
            float av[8] = {a0.x, a0.y, a0.z, a0.w, a1.x, a1.y, a1.z, a1.w};
#pragma unroll
            for (int i = 0; i < 8; i++) {
                unsigned long long aa = pack2(av[i], av[i]);
                fma2(acc[i][0], aa, bb0);
                fma2(acc[i][1], aa, bb1);
                fma2(acc[i][2], aa, bb2);
                fma2(acc[i][3], aa, bb3);
            }
        }
        __syncthreads();
    }

    float C[8][8];
#pragma unroll
    for (int i = 0; i < 8; i++)
#pragma unroll
        for (int jp = 0; jp < 4; jp++)
            unpack2(acc[i][jp], C[i][2 * jp], C[i][2 * jp + 1]);

    // Transposed epilogue: for each owned output channel o, the 8 owned l's
    // are consecutive -> two float4 stores along L.
#pragma unroll
    for (int j = 0; j < 8; j++) {
        int o = n0 + col0 + j;
        float bj = bo[o];
        float* p = out + ((size_t)b * DOUT + o) * LEN + l0 + row0;
        *(float4*)p       = make_float4(C[0][j] + bj, C[1][j] + bj,
                                        C[2][j] + bj, C[3][j] + bj);
        *(float4*)(p + 4) = make_float4(C[4][j] + bj, C[5][j] + bj,
                                        C[6][j] + bj, C[7][j] + bj);
    }
}

// ---------------- launch ----------------
extern "C" void kernel_launch(void* const* d_in, const int* in_sizes, int n_in,
                              void* d_out, int out_size)
{
    const float* x  = (const float*)d_in[0];
    const float* Wq = (const float*)d_in[1];
    const float* bq = (const float*)d_in[2];
    const float* Wk = (const float*)d_in[3];
    const float* bk = (const float*)d_in[4];
    const float* Wv = (const float*)d_in[5];
    const float* bv = (const float*)d_in[6];
    const float* Wo = (const float*)d_in[7];
    const float* bo = (const float*)d_in[8];
    float* out = (float*)d_out;

    qkv_gemm<<<dim3(MTOT / BM, 12), 256>>>(x, Wq, bq, Wk, bk, Wv, bv);
    attn_kernel<<<(BATCH * LEN * NHEAD) / 8, 256>>>();
    out_gemm<<<dim3(MTOT / BM, DOUT / BN), 256>>>(Wo, bo, out);
}

// round 3
// speedup vs baseline: 1.9847x; 1.9847x over previous
#include <cuda_runtime.h>
#include <cstdint>

// ---------------- problem constants ----------------
#define BATCH 8
#define NHID 256
#define LEN 2048
#define NHEAD 8
#define HDIM 64
#define DQKV 512
#define DOUT 2048
#define MTOT (BATCH * LEN)   // 16384

// ---------------- GEMM tiling ----------------
#define BM 128
#define BN 128
#define BK 32
#define PA 136                       // smem pitch (floats): conflict-free frag loads
#define ASZ (BK * PA)                // 4352 floats per buffer
#define EPP 132                      // epilogue bounce pitch
#define SMEM_DYN (4 * ASZ * 4)       // 69632 bytes (A0,A1,B0,B1); >= ep tile 67584

// Scratch (allocation-free: __device__ globals)
__device__ float g_qkv[(size_t)MTOT * 1536];      // [m][0:512]=q [512:1024]=k [1024:1536]=v
__device__ float g_att_t[(size_t)DQKV * MTOT];    // attention output, TRANSPOSED [d][m]

// ---------------- helpers ----------------
__device__ __forceinline__ uint32_t tf32r(float f) {
    uint32_t u;
    asm("cvt.rna.tf32.f32 %0, %1;" : "=r"(u) : "f"(f));
    return u;
}
__device__ __forceinline__ void mma8(float& d0, float& d1, float& d2, float& d3,
                                     uint32_t a0, uint32_t a1, uint32_t a2, uint32_t a3,
                                     uint32_t b0, uint32_t b1) {
    asm volatile(
        "mma.sync.aligned.m16n8k8.row.col.f32.tf32.tf32.f32 "
        "{%0,%1,%2,%3}, {%4,%5,%6,%7}, {%8,%9}, {%0,%1,%2,%3};"
        : "+f"(d0), "+f"(d1), "+f"(d2), "+f"(d3)
        : "r"(a0), "r"(a1), "r"(a2), "r"(a3), "r"(b0), "r"(b1));
}

// mma over one staged (A,B) tile pair. acc[fm][fn][r]
__device__ __forceinline__ void mma_tile(const float* __restrict__ Ab,
                                         const float* __restrict__ Bb,
                                         float acc[2][8][4], int mw, int nw,
                                         int c, int g) {
#pragma unroll
    for (int ks = 0; ks < BK; ks += 8) {
        uint32_t a[2][4];
#pragma unroll
        for (int fm = 0; fm < 2; fm++) {
            const float* p = Ab + (ks + c) * PA + mw + fm * 16 + g;
            a[fm][0] = __float_as_uint(p[0]);
            a[fm][1] = __float_as_uint(p[8]);
            a[fm][2] = __float_as_uint(p[4 * PA]);
            a[fm][3] = __float_as_uint(p[4 * PA + 8]);
        }
#pragma unroll
        for (int fn = 0; fn < 8; fn++) {
            const float* q = Bb + (ks + c) * PA + nw + fn * 8 + g;
            uint32_t b0 = __float_as_uint(q[0]);
            uint32_t b1 = __float_as_uint(q[4 * PA]);
            mma8(acc[0][fn][0], acc[0][fn][1], acc[0][fn][2], acc[0][fn][3],
                 a[0][0], a[0][1], a[0][2], a[0][3], b0, b1);
            mma8(acc[1][fn][0], acc[1][fn][1], acc[1][fn][2], acc[1][fn][3],
                 a[1][0], a[1][1], a[1][2], a[1][3], b0, b1);
        }
    }
}

// Tile staging macros: 4 float4 each for A and B per thread.
// f = tid + j*256 -> k = f>>5 (0..31), m4 = (f&31)*4 (0..124)
#define LDTILE(k0, Ag, RSA, Bg, RSB)                                          \
    {                                                                         \
        _Pragma("unroll") for (int j = 0; j < 4; j++) {                       \
            int f = tid + j * 256;                                            \
            int kk = f >> 5, m4 = (f & 31) * 4;                               \
            ra[j] = *(const float4*)((Ag) + (size_t)((k0) + kk) * (RSA) + m4);\
            rb[j] = *(const float4*)((Bg) + (size_t)((k0) + kk) * (RSB) + m4);\
        }                                                                     \
    }
#define STTILE(Ad, Bd)                                                        \
    {                                                                         \
        _Pragma("unroll") for (int j = 0; j < 4; j++) {                       \
            int f = tid + j * 256;                                            \
            int kk = f >> 5, m4 = (f & 31) * 4;                               \
            *(uint4*)((Ad) + kk * PA + m4) =                                  \
                make_uint4(tf32r(ra[j].x), tf32r(ra[j].y),                    \
                           tf32r(ra[j].z), tf32r(ra[j].w));                   \
            *(uint4*)((Bd) + kk * PA + m4) =                                  \
                make_uint4(tf32r(rb[j].x), tf32r(rb[j].y),                    \
                           tf32r(rb[j].z), tf32r(rb[j].w));                   \
        }                                                                     \
    }

// ---------------- Kernel 1: QKV projection ----------------
// C[16384 x 1536] = A[16384 x 256] @ W[256 x 512] (x3 weights); A[m][k] = x[b][k][l]
__global__ __launch_bounds__(256, 1) void qkv_mma(
    const float* __restrict__ x,
    const float* __restrict__ Wq, const float* __restrict__ bq,
    const float* __restrict__ Wk, const float* __restrict__ bk,
    const float* __restrict__ Wv, const float* __restrict__ bv)
{
    extern __shared__ float sm[];
    float* Abuf[2] = {sm, sm + ASZ};
    float* Bbuf[2] = {sm + 2 * ASZ, sm + 3 * ASZ};

    const int tid = threadIdx.x, lane = tid & 31, wid = tid >> 5;
    const int c = lane & 3, g = lane >> 2;
    const int mw = (wid & 3) * 32, nw = (wid >> 2) * 64;

    const int m0 = blockIdx.x * BM;
    const int bb = m0 >> 11;
    const int l0 = m0 & (LEN - 1);
    const int yy = blockIdx.y;               // 0..11
    const int mat = yy >> 2;                 // 0=q 1=k 2=v
    const int n0 = (yy & 3) * BN;

    const float* W    = (mat == 0) ? Wq : (mat == 1) ? Wk : Wv;
    const float* bias = (mat == 0) ? bq : (mat == 1) ? bk : bv;
    const float* Ag = x + (size_t)bb * NHID * LEN + l0;   // [k][l] rows
    const float* Bg = W + n0;                             // [k][n], row stride 512

    float acc[2][8][4];
#pragma unroll
    for (int i = 0; i < 2; i++)
#pragma unroll
        for (int j = 0; j < 8; j++)
#pragma unroll
            for (int r = 0; r < 4; r++) acc[i][j][r] = 0.f;

    float4 ra[4], rb[4];
    LDTILE(0, Ag, LEN, Bg, DQKV);
    STTILE(Abuf[0], Bbuf[0]);
    __syncthreads();

    const int NCH = NHID / BK;  // 8
    for (int cc = 0; cc < NCH; cc++) {
        const int cur = cc & 1, nxt = cur ^ 1;
        if (cc + 1 < NCH) LDTILE((cc + 1) * BK, Ag, LEN, Bg, DQKV);
        mma_tile(Abuf[cur], Bbuf[cur], acc, mw, nw, c, g);
        if (cc + 1 < NCH) STTILE(Abuf[nxt], Bbuf[nxt]);
        __syncthreads();
    }

    // Epilogue: direct float2 stores (c0,c1 adjacent cols; c2,c3 at m+8)
#pragma unroll
    for (int fm = 0; fm < 2; fm++)
#pragma unroll
        for (int fn = 0; fn < 8; fn++) {
            int m = m0 + mw + fm * 16 + g;
            int n = nw + fn * 8 + c * 2;
            float bx = __ldg(bias + n0 + n), by = __ldg(bias + n0 + n + 1);
            float* p = g_qkv + (size_t)m * 1536 + mat * 512 + n0 + n;
            *(float2*)p = make_float2(acc[fm][fn][0] + bx, acc[fm][fn][1] + by);
            *(float2*)(p + (size_t)8 * 1536) =
                make_float2(acc[fm][fn][2] + bx, acc[fm][fn][3] + by);
        }
}

// ---------------- Kernel 2: window-3 attention, transposed output ----------------
// block = (b, head, 32 l's); output g_att_t[d][m] via smem bounce.
__global__ __launch_bounds__(256) void attn_t()
{
    __shared__ float att_s[32 * 66];   // [li][d] pitch 66
    const int tid = threadIdx.x, warp = tid >> 5, lane = tid & 31;
    const int bid = blockIdx.x;
    const int b = bid >> 9;
    const int head = (bid >> 6) & 7;
    const int l0 = (bid & 63) * 32;

#pragma unroll
    for (int i = 0; i < 4; i++) {
        const int li = warp * 4 + i;
        const int l = l0 + li;
        const size_t mrow = (size_t)b * LEN + l;
        const float* base = g_qkv + mrow * 1536 + head * HDIM + lane * 2;
        const float2 qv = *(const float2*)base;

        float  s[3];
        float2 vv[3];
#pragma unroll
        for (int w = 0; w < 3; w++) {
            int lw = l + w - 1;
            bool ok = (unsigned)lw < (unsigned)LEN;
            float2 kv = make_float2(0.f, 0.f);
            vv[w] = make_float2(0.f, 0.f);
            if (ok) {
                const float* pw = base + (size_t)(w - 1) * 1536;
                kv    = *(const float2*)(pw + 512);
                vv[w] = *(const float2*)(pw + 1024);
            }
            float p = qv.x * kv.x + qv.y * kv.y;
            p += __shfl_xor_sync(0xffffffffu, p, 16);
            p += __shfl_xor_sync(0xffffffffu, p, 8);
            p += __shfl_xor_sync(0xffffffffu, p, 4);
            p += __shfl_xor_sync(0xffffffffu, p, 2);
            p += __shfl_xor_sync(0xffffffffu, p, 1);
            s[w] = p * 0.125f;  // 1/sqrt(64)
        }

        float mx = fmaxf(s[0], fmaxf(s[1], s[2]));
        float e0 = expf(s[0] - mx), e1 = expf(s[1] - mx), e2 = expf(s[2] - mx);
        float inv = 1.0f / (e0 + e1 + e2);
        float ax = (e0 * vv[0].x + e1 * vv[1].x + e2 * vv[2].x) * inv;
        float ay = (e0 * vv[0].y + e1 * vv[1].y + e2 * vv[2].y) * inv;
        *(float2*)&att_s[li * 66 + lane * 2] = make_float2(ax, ay);
    }
    __syncthreads();

    // write g_att_t[(head*64+d)][b*2048 + l0 + 0..31], float4 along l
#pragma unroll
    for (int i = 0; i < 2; i++) {
        int f = tid + i * 256;
        int d = f >> 3;                 // 0..63
        int q4 = (f & 7) * 4;           // 0..28
        float4 v = make_float4(att_s[(q4 + 0) * 66 + d],
                               att_s[(q4 + 1) * 66 + d],
                               att_s[(q4 + 2) * 66 + d],
                               att_s[(q4 + 3) * 66 + d]);
        *(float4*)(g_att_t + ((size_t)(head * HDIM + d)) * MTOT
                   + (size_t)b * LEN + l0 + q4) = v;
    }
}

// ---------------- Kernel 3: output projection + transposed write ----------------
// out[b][o][l] = att[m][512] @ Wo[512][2048] + bo;  A staged from g_att_t [k][m]
__global__ __launch_bounds__(256, 1) void out_mma(
    const float* __restrict__ Wo, const float* __restrict__ bo,
    float* __restrict__ out)
{
    extern __shared__ float sm[];
    float* Abuf[2] = {sm, sm + ASZ};
    float* Bbuf[2] = {sm + 2 * ASZ, sm + 3 * ASZ};

    const int tid = threadIdx.x, lane = tid & 31, wid = tid >> 5;
    const int c = lane & 3, g = lane >> 2;
    const int mw = (wid & 3) * 32, nw = (wid >> 2) * 64;

    const int m0 = blockIdx.x * BM;
    const int bb = m0 >> 11;
    const int l0 = m0 & (LEN - 1);
    const int n0 = blockIdx.y * BN;

    const float* Ag = g_att_t + m0;     // [k][m], row stride 16384
    const float* Bg = Wo + n0;          // [k][n], row stride 2048

    float acc[2][8][4];
#pragma unroll
    for (int i = 0; i < 2; i++)
#pragma unroll
        for (int j = 0; j < 8; j++)
#pragma unroll
            for (int r = 0; r < 4; r++) acc[i][j][r] = 0.f;

    float4 ra[4], rb[4];
    LDTILE(0, Ag, MTOT, Bg, DOUT);
    STTILE(Abuf[0], Bbuf[0]);
    __syncthreads();

    const int NCH = DQKV / BK;  // 16
    for (int cc = 0; cc < NCH; cc++) {
        const int cur = cc & 1, nxt = cur ^ 1;
        if (cc + 1 < NCH) LDTILE((cc + 1) * BK, Ag, MTOT, Bg, DOUT);
        mma_tile(Abuf[cur], Bbuf[cur], acc, mw, nw, c, g);
        if (cc + 1 < NCH) STTILE(Abuf[nxt], Bbuf[nxt]);
        __syncthreads();
    }

    // Epilogue: bounce C through smem as [n][m] (pitch 132), then 128B stores along l
    float* ep = sm;   // 128*132 floats = 67584 B <= SMEM_DYN
#pragma unroll
    for (int fm = 0; fm < 2; fm++)
#pragma unroll
        for (int fn = 0; fn < 8; fn++) {
            int nrel = nw + fn * 8 + c * 2;
            int mrel = mw + fm * 16 + g;
            ep[nrel * EPP + mrel]           = acc[fm][fn][0];
            ep[(nrel + 1) * EPP + mrel]     = acc[fm][fn][1];
            ep[nrel * EPP + mrel + 8]       = acc[fm][fn][2];
            ep[(nrel + 1) * EPP + mrel + 8] = acc[fm][fn][3];
        }
    __syncthreads();
#pragma unroll
    for (int i = 0; i < 16; i++) {
        int f = tid + i * 256;
        int nr = f >> 5;                // 0..127
        int m4 = (f & 31) * 4;          // 0..124
        float4 v = *(float4*)&ep[nr * EPP + m4];
        float bj = __ldg(bo + n0 + nr);
        v.x += bj; v.y += bj; v.z += bj; v.w += bj;
        *(float4*)(out + ((size_t)(bb * DOUT + n0 + nr)) * LEN + l0 + m4) = v;
    }
}

// ---------------- launch ----------------
extern "C" void kernel_launch(void* const* d_in, const int* in_sizes, int n_in,
                              void* d_out, int out_size)
{
    const float* x  = (const float*)d_in[0];
    const float* Wq = (const float*)d_in[1];
    const float* bq = (const float*)d_in[2];
    const float* Wk = (const float*)d_in[3];
    const float* bk = (const float*)d_in[4];
    const float* Wv = (const float*)d_in[5];
    const float* bv = (const float*)d_in[6];
    const float* Wo = (const float*)d_in[7];
    const float* bo = (const float*)d_in[8];
    float* out = (float*)d_out;

    cudaFuncSetAttribute(qkv_mma, cudaFuncAttributeMaxDynamicSharedMemorySize, SMEM_DYN);
    cudaFuncSetAttribute(out_mma, cudaFuncAttributeMaxDynamicSharedMemorySize, SMEM_DYN);

    qkv_mma<<<dim3(MTOT / BM, 12), 256, SMEM_DYN>>>(x, Wq, bq, Wk, bk, Wv, bv);
    attn_t<<<BATCH * NHEAD * (LEN / 32), 256>>>();
    out_mma<<<dim3(MTOT / BM, DOUT / BN), 256, SMEM_DYN>>>(Wo, bo, out);
}

// round 4
// speedup vs baseline: 3.0546x; 1.5391x over previous
#include <cuda_runtime.h>
#include <cstdint>

// ---------------- problem constants ----------------
#define BATCH 8
#define NHID 256
#define LEN 2048
#define NHEAD 8
#define HDIM 64
#define DQKV 512
#define DOUT 2048
#define MTOT (BATCH * LEN)   // 16384

// ---------------- GEMM tiling ----------------
#define BM 128
#define BN 128
#define BK 32
#define PA 136                       // smem pitch (floats): conflict-free frag loads
#define ASZ (BK * PA)                // 4352 floats per buffer
#define EPP 132                      // epilogue bounce pitch
#define SMEM_DYN (4 * ASZ * 4)       // 69632 bytes (A0,A1,B0,B1); >= ep tile 67584

// Scratch (allocation-free: __device__ globals). All tf32-pre-rounded operands.
__device__ float g_x[(size_t)BATCH * NHID * LEN];   // rounded copy of x
__device__ float g_wq[NHID * DQKV];
__device__ float g_wk[NHID * DQKV];
__device__ float g_wv[NHID * DQKV];
__device__ float g_wo[DQKV * DOUT];
__device__ float g_qkv[(size_t)MTOT * 1536];        // fp32 q/k/v (attention input)
__device__ float g_att_t[(size_t)DQKV * MTOT];      // attention out, transposed, rounded

// ---------------- helpers ----------------
__device__ __forceinline__ uint32_t tf32r(float f) {
    uint32_t u;
    asm("cvt.rna.tf32.f32 %0, %1;" : "=r"(u) : "f"(f));
    return u;
}
__device__ __forceinline__ uint32_t smem_u32(const void* p) {
    uint32_t a;
    asm("{ .reg .u64 t; cvta.to.shared.u64 t, %1; cvt.u32.u64 %0, t; }" : "=r"(a) : "l"(p));
    return a;
}
__device__ __forceinline__ void cpa16(uint32_t dst, const void* src) {
    asm volatile("cp.async.cg.shared.global [%0], [%1], 16;" :: "r"(dst), "l"(src));
}
#define CP_COMMIT() asm volatile("cp.async.commit_group;" ::: "memory")
#define CP_WAIT(n)  asm volatile("cp.async.wait_group %0;" :: "n"(n) : "memory")

__device__ __forceinline__ void mma8(float& d0, float& d1, float& d2, float& d3,
                                     uint32_t a0, uint32_t a1, uint32_t a2, uint32_t a3,
                                     uint32_t b0, uint32_t b1) {
    asm volatile(
        "mma.sync.aligned.m16n8k8.row.col.f32.tf32.tf32.f32 "
        "{%0,%1,%2,%3}, {%4,%5,%6,%7}, {%8,%9}, {%0,%1,%2,%3};"
        : "+f"(d0), "+f"(d1), "+f"(d2), "+f"(d3)
        : "r"(a0), "r"(a1), "r"(a2), "r"(a3), "r"(b0), "r"(b1));
}

// mma over one staged (A,B) tile pair. acc[fm][fn][r]
__device__ __forceinline__ void mma_tile(const float* __restrict__ Ab,
                                         const float* __restrict__ Bb,
                                         float acc[2][8][4], int mw, int nw,
                                         int c, int g) {
#pragma unroll
    for (int ks = 0; ks < BK; ks += 8) {
        uint32_t a[2][4];
#pragma unroll
        for (int fm = 0; fm < 2; fm++) {
            const float* p = Ab + (ks + c) * PA + mw + fm * 16 + g;
            a[fm][0] = __float_as_uint(p[0]);
            a[fm][1] = __float_as_uint(p[8]);
            a[fm][2] = __float_as_uint(p[4 * PA]);
            a[fm][3] = __float_as_uint(p[4 * PA + 8]);
        }
#pragma unroll
        for (int fn = 0; fn < 8; fn++) {
            const float* q = Bb + (ks + c) * PA + nw + fn * 8 + g;
            uint32_t b0 = __float_as_uint(q[0]);
            uint32_t b1 = __float_as_uint(q[4 * PA]);
            mma8(acc[0][fn][0], acc[0][fn][1], acc[0][fn][2], acc[0][fn][3],
                 a[0][0], a[0][1], a[0][2], a[0][3], b0, b1);
            mma8(acc[1][fn][0], acc[1][fn][1], acc[1][fn][2], acc[1][fn][3],
                 a[1][0], a[1][1], a[1][2], a[1][3], b0, b1);
        }
    }
}

// Issue one (A,B) k-chunk into buffer `buf` via cp.async. Per thread: 8x16B.
#define ISSUE_TILE(buf, k0)                                                   \
    {                                                                         \
        _Pragma("unroll") for (int j = 0; j < 4; j++) {                       \
            cpa16(aAddr[buf] + sdst + j * (8 * PA * 4),                       \
                  aS + (size_t)((k0) + 8 * j) * RSA);                         \
            cpa16(bAddr[buf] + sdst + j * (8 * PA * 4),                       \
                  bS + (size_t)((k0) + 8 * j) * RSB);                         \
        }                                                                     \
        CP_COMMIT();                                                          \
    }

// ---------------- prep: tf32 rounding pass ----------------
__global__ __launch_bounds__(256) void cvt_tf32(const float4* __restrict__ src,
                                                float4* __restrict__ dst, int n4) {
    int i = blockIdx.x * 256 + threadIdx.x;
    if (i < n4) {
        float4 v = src[i];
        uint4 u = make_uint4(tf32r(v.x), tf32r(v.y), tf32r(v.z), tf32r(v.w));
        *(uint4*)&dst[i] = u;
    }
}

// ---------------- Kernel 1: QKV projection ----------------
// C[16384 x 1536] = A[16384 x 256] @ W[256 x 512] (x3); A[m][k] = g_x[b][k][l]
__global__ __launch_bounds__(256, 2) void qkv_mma(
    const float* __restrict__ bq, const float* __restrict__ bk,
    const float* __restrict__ bv)
{
    extern __shared__ float sm[];
    const int tid = threadIdx.x, lane = tid & 31, wid = tid >> 5;
    const int c = lane & 3, g = lane >> 2;
    const int mw = (wid & 3) * 32, nw = (wid >> 2) * 64;

    const int m0 = blockIdx.x * BM;
    const int bb = m0 >> 11;
    const int l0 = m0 & (LEN - 1);
    const int yy = blockIdx.y;               // 0..11
    const int mat = yy >> 2;                 // 0=q 1=k 2=v
    const int n0 = (yy & 3) * BN;

    const float* W    = (mat == 0) ? g_wq : (mat == 1) ? g_wk : g_wv;
    const float* bias = (mat == 0) ? bq : (mat == 1) ? bk : bv;

    const size_t RSA = LEN, RSB = DQKV;
    const int kk0 = tid >> 5, m4s = (tid & 31) * 4;
    const uint32_t sbase = smem_u32(sm);
    const uint32_t sdst = (uint32_t)(kk0 * PA + m4s) * 4;
    const uint32_t aAddr[2] = {sbase, sbase + ASZ * 4};
    const uint32_t bAddr[2] = {sbase + 2 * ASZ * 4, sbase + 3 * ASZ * 4};
    const float* aS = g_x + (size_t)bb * NHID * LEN + l0 + (size_t)kk0 * RSA + m4s;
    const float* bS = W + n0 + (size_t)kk0 * RSB + m4s;

    float acc[2][8][4];
#pragma unroll
    for (int i = 0; i < 2; i++)
#pragma unroll
        for (int j = 0; j < 8; j++)
#pragma unroll
            for (int r = 0; r < 4; r++) acc[i][j][r] = 0.f;

    ISSUE_TILE(0, 0);
    const int NCH = NHID / BK;  // 8
    for (int cc = 0; cc < NCH; cc++) {
        const int cur = cc & 1;
        if (cc + 1 < NCH) { ISSUE_TILE(cur ^ 1, (cc + 1) * BK); CP_WAIT(1); }
        else              { CP_WAIT(0); }
        __syncthreads();
        mma_tile(sm + cur * ASZ, sm + (2 + cur) * ASZ, acc, mw, nw, c, g);
        __syncthreads();
    }

    // Epilogue: direct float2 stores
#pragma unroll
    for (int fm = 0; fm < 2; fm++)
#pragma unroll
        for (int fn = 0; fn < 8; fn++) {
            int m = m0 + mw + fm * 16 + g;
            int n = nw + fn * 8 + c * 2;
            float bx = __ldg(bias + n0 + n), by = __ldg(bias + n0 + n + 1);
            float* p = g_qkv + (size_t)m * 1536 + mat * 512 + n0 + n;
            *(float2*)p = make_float2(acc[fm][fn][0] + bx, acc[fm][fn][1] + by);
            *(float2*)(p + (size_t)8 * 1536) =
                make_float2(acc[fm][fn][2] + bx, acc[fm][fn][3] + by);
        }
}

// ---------------- Kernel 2: window-3 attention, transposed+rounded output ----------------
__global__ __launch_bounds__(256) void attn_t()
{
    __shared__ float att_s[32 * 66];   // [li][d] pitch 66
    const int tid = threadIdx.x, warp = tid >> 5, lane = tid & 31;
    const int bid = blockIdx.x;
    const int b = bid >> 9;
    const int head = (bid >> 6) & 7;
    const int l0 = (bid & 63) * 32;

#pragma unroll
    for (int i = 0; i < 4; i++) {
        const int li = warp * 4 + i;
        const int l = l0 + li;
        const size_t mrow = (size_t)b * LEN + l;
        const float* base = g_qkv + mrow * 1536 + head * HDIM + lane * 2;
        const float2 qv = *(const float2*)base;

        float  s[3];
        float2 vv[3];
#pragma unroll
        for (int w = 0; w < 3; w++) {
            int lw = l + w - 1;
            bool ok = (unsigned)lw < (unsigned)LEN;
            float2 kv = make_float2(0.f, 0.f);
            vv[w] = make_float2(0.f, 0.f);
            if (ok) {
                const float* pw = base + (size_t)(w - 1) * 1536;
                kv    = *(const float2*)(pw + 512);
                vv[w] = *(const float2*)(pw + 1024);
            }
            float p = qv.x * kv.x + qv.y * kv.y;
            p += __shfl_xor_sync(0xffffffffu, p, 16);
            p += __shfl_xor_sync(0xffffffffu, p, 8);
            p += __shfl_xor_sync(0xffffffffu, p, 4);
            p += __shfl_xor_sync(0xffffffffu, p, 2);
            p += __shfl_xor_sync(0xffffffffu, p, 1);
            s[w] = p * 0.125f;  // 1/sqrt(64)
        }

        float mx = fmaxf(s[0], fmaxf(s[1], s[2]));
        float e0 = expf(s[0] - mx), e1 = expf(s[1] - mx), e2 = expf(s[2] - mx);
        float inv = 1.0f / (e0 + e1 + e2);
        float ax = (e0 * vv[0].x + e1 * vv[1].x + e2 * vv[2].x) * inv;
        float ay = (e0 * vv[0].y + e1 * vv[1].y + e2 * vv[2].y) * inv;
        *(float2*)&att_s[li * 66 + lane * 2] = make_float2(ax, ay);
    }
    __syncthreads();

    // write g_att_t[(head*64+d)][b*2048 + l0 + 0..31], float4 along l, tf32-rounded
#pragma unroll
    for (int i = 0; i < 2; i++) {
        int f = tid + i * 256;
        int d = f >> 3;                 // 0..63
        int q4 = (f & 7) * 4;           // 0..28
        uint4 v = make_uint4(tf32r(att_s[(q4 + 0) * 66 + d]),
                             tf32r(att_s[(q4 + 1) * 66 + d]),
                             tf32r(att_s[(q4 + 2) * 66 + d]),
                             tf32r(att_s[(q4 + 3) * 66 + d]));
        *(uint4*)(g_att_t + ((size_t)(head * HDIM + d)) * MTOT
                  + (size_t)b * LEN + l0 + q4) = v;
    }
}

// ---------------- Kernel 3: output projection + transposed write ----------------
// out[b][o][l] = att[m][512] @ Wo[512][2048] + bo;  A from g_att_t [k][m]
__global__ __launch_bounds__(256, 2) void out_mma(
    const float* __restrict__ bo, float* __restrict__ out)
{
    extern __shared__ float sm[];
    const int tid = threadIdx.x, lane = tid & 31, wid = tid >> 5;
    const int c = lane & 3, g = lane >> 2;
    const int mw = (wid & 3) * 32, nw = (wid >> 2) * 64;

    const int m0 = blockIdx.x * BM;
    const int bb = m0 >> 11;
    const int l0 = m0 & (LEN - 1);
    const int n0 = blockIdx.y * BN;

    const size_t RSA = MTOT, RSB = DOUT;
    const int kk0 = tid >> 5, m4s = (tid & 31) * 4;
    const uint32_t sbase = smem_u32(sm);
    const uint32_t sdst = (uint32_t)(kk0 * PA + m4s) * 4;
    const uint32_t aAddr[2] = {sbase, sbase + ASZ * 4};
    const uint32_t bAddr[2] = {sbase + 2 * ASZ * 4, sbase + 3 * ASZ * 4};
    const float* aS = g_att_t + m0 + (size_t)kk0 * RSA + m4s;
    const float* bS = g_wo + n0 + (size_t)kk0 * RSB + m4s;

    float acc[2][8][4];
#pragma unroll
    for (int i = 0; i < 2; i++)
#pragma unroll
        for (int j = 0; j < 8; j++)
#pragma unroll
            for (int r = 0; r < 4; r++) acc[i][j][r] = 0.f;

    ISSUE_TILE(0, 0);
    const int NCH = DQKV / BK;  // 16
    for (int cc = 0; cc < NCH; cc++) {
        const int cur = cc & 1;
        if (cc + 1 < NCH) { ISSUE_TILE(cur ^ 1, (cc + 1) * BK); CP_WAIT(1); }
        else              { CP_WAIT(0); }
        __syncthreads();
        mma_tile(sm + cur * ASZ, sm + (2 + cur) * ASZ, acc, mw, nw, c, g);
        __syncthreads();
    }

    // Epilogue: bounce C through smem as [n][m], then 128B stores along l
    float* ep = sm;   // 128*132 floats = 67584 B <= SMEM_DYN
#pragma unroll
    for (int fm = 0; fm < 2; fm++)
#pragma unroll
        for (int fn = 0; fn < 8; fn++) {
            int nrel = nw + fn * 8 + c * 2;
            int mrel = mw + fm * 16 + g;
            ep[nrel * EPP + mrel]           = acc[fm][fn][0];
            ep[(nrel + 1) * EPP + mrel]     = acc[fm][fn][1];
            ep[nrel * EPP + mrel + 8]       = acc[fm][fn][2];
            ep[(nrel + 1) * EPP + mrel + 8] = acc[fm][fn][3];
        }
    __syncthreads();
#pragma unroll
    for (int i = 0; i < 16; i++) {
        int f = tid + i * 256;
        int nr = f >> 5;                // 0..127
        int m4 = (f & 31) * 4;          // 0..124
        float4 v = *(float4*)&ep[nr * EPP + m4];
        float bj = __ldg(bo + n0 + nr);
        v.x += bj; v.y += bj; v.z += bj; v.w += bj;
        *(float4*)(out + ((size_t)(bb * DOUT + n0 + nr)) * LEN + l0 + m4) = v;
    }
}

// ---------------- launch ----------------
extern "C" void kernel_launch(void* const* d_in, const int* in_sizes, int n_in,
                              void* d_out, int out_size)
{
    const float* x  = (const float*)d_in[0];
    const float* Wq = (const float*)d_in[1];
    const float* bq = (const float*)d_in[2];
    const float* Wk = (const float*)d_in[3];
    const float* bk = (const float*)d_in[4];
    const float* Wv = (const float*)d_in[5];
    const float* bv = (const float*)d_in[6];
    const float* Wo = (const float*)d_in[7];
    const float* bo = (const float*)d_in[8];
    float* out = (float*)d_out;

    cudaFuncSetAttribute(qkv_mma, cudaFuncAttributeMaxDynamicSharedMemorySize, SMEM_DYN);
    cudaFuncSetAttribute(out_mma, cudaFuncAttributeMaxDynamicSharedMemorySize, SMEM_DYN);

    // tf32 pre-rounding of all GEMM operands
    float* gx;  cudaGetSymbolAddress((void**)&gx,  g_x);
    float* gwq; cudaGetSymbolAddress((void**)&gwq, g_wq);
    float* gwk; cudaGetSymbolAddress((void**)&gwk, g_wk);
    float* gwv; cudaGetSymbolAddress((void**)&gwv, g_wv);
    float* gwo; cudaGetSymbolAddress((void**)&gwo, g_wo);
    const int NX = BATCH * NHID * LEN / 4, NW = NHID * DQKV / 4, NO = DQKV * DOUT / 4;
    cvt_tf32<<<(NX + 255) / 256, 256>>>((const float4*)x,  (float4*)gx,  NX);
    cvt_tf32<<<(NW + 255) / 256, 256>>>((const float4*)Wq, (float4*)gwq, NW);
    cvt_tf32<<<(NW + 255) / 256, 256>>>((const float4*)Wk, (float4*)gwk, NW);
    cvt_tf32<<<(NW + 255) / 256, 256>>>((const float4*)Wv, (float4*)gwv, NW);
    cvt_tf32<<<(NO + 255) / 256, 256>>>((const float4*)Wo, (float4*)gwo, NO);

    qkv_mma<<<dim3(MTOT / BM, 12), 256, SMEM_DYN>>>(bq, bk, bv);
    attn_t<<<BATCH * NHEAD * (LEN / 32), 256>>>();
    out_mma<<<dim3(MTOT / BM, DOUT / BN), 256, SMEM_DYN>>>(bo, out);
}

// round 5
// speedup vs baseline: 3.1296x; 1.0245x over previous
#include <cuda_runtime.h>
#include <cstdint>

// ---------------- problem constants ----------------
#define BATCH 8
#define NHID 256
#define LEN 2048
#define NHEAD 8
#define HDIM 64
#define DQKV 512
#define DOUT 2048
#define MTOT (BATCH * LEN)   // 16384

// ---------------- GEMM tiling ----------------
#define BM 128
#define BN 128
#define BK 32
#define PA 136                       // smem pitch (floats): conflict-free frag loads
#define ASZ (BK * PA)                // 4352 floats per buffer
#define EPP 132                      // epilogue bounce pitch
#define NSTAGE 3
#define SMEM_DYN (2 * NSTAGE * ASZ * 4)   // 104448 bytes; >= ep tile 67584

// Scratch (allocation-free: __device__ globals). All tf32-pre-rounded operands.
__device__ float g_x[(size_t)BATCH * NHID * LEN];   // rounded copy of x
__device__ float g_wq[NHID * DQKV];
__device__ float g_wk[NHID * DQKV];
__device__ float g_wv[NHID * DQKV];
__device__ float g_wo[DQKV * DOUT];
__device__ float g_qkv[(size_t)MTOT * 1536];        // fp32 q/k/v (attention input)
__device__ float g_att_t[(size_t)DQKV * MTOT];      // attention out, transposed, rounded

// ---------------- helpers ----------------
__device__ __forceinline__ uint32_t tf32r(float f) {
    uint32_t u;
    asm("cvt.rna.tf32.f32 %0, %1;" : "=r"(u) : "f"(f));
    return u;
}
__device__ __forceinline__ uint32_t smem_u32(const void* p) {
    uint32_t a;
    asm("{ .reg .u64 t; cvta.to.shared.u64 t, %1; cvt.u32.u64 %0, t; }" : "=r"(a) : "l"(p));
    return a;
}
__device__ __forceinline__ void cpa16(uint32_t dst, const void* src) {
    asm volatile("cp.async.cg.shared.global [%0], [%1], 16;" :: "r"(dst), "l"(src));
}
#define CP_COMMIT() asm volatile("cp.async.commit_group;" ::: "memory")
#define CP_WAIT(n)  asm volatile("cp.async.wait_group %0;" :: "n"(n) : "memory")

__device__ __forceinline__ void mma8(float& d0, float& d1, float& d2, float& d3,
                                     uint32_t a0, uint32_t a1, uint32_t a2, uint32_t a3,
                                     uint32_t b0, uint32_t b1) {
    asm volatile(
        "mma.sync.aligned.m16n8k8.row.col.f32.tf32.tf32.f32 "
        "{%0,%1,%2,%3}, {%4,%5,%6,%7}, {%8,%9}, {%0,%1,%2,%3};"
        : "+f"(d0), "+f"(d1), "+f"(d2), "+f"(d3)
        : "r"(a0), "r"(a1), "r"(a2), "r"(a3), "r"(b0), "r"(b1));
}

// mma over one staged (A,B) tile pair. acc[fm][fn][r]
__device__ __forceinline__ void mma_tile(const float* __restrict__ Ab,
                                         const float* __restrict__ Bb,
                                         float acc[2][8][4], int mw, int nw,
                                         int c, int g) {
#pragma unroll
    for (int ks = 0; ks < BK; ks += 8) {
        uint32_t a[2][4];
#pragma unroll
        for (int fm = 0; fm < 2; fm++) {
            const float* p = Ab + (ks + c) * PA + mw + fm * 16 + g;
            a[fm][0] = __float_as_uint(p[0]);
            a[fm][1] = __float_as_uint(p[8]);
            a[fm][2] = __float_as_uint(p[4 * PA]);
            a[fm][3] = __float_as_uint(p[4 * PA + 8]);
        }
#pragma unroll
        for (int fn = 0; fn < 8; fn++) {
            const float* q = Bb + (ks + c) * PA + nw + fn * 8 + g;
            uint32_t b0 = __float_as_uint(q[0]);
            uint32_t b1 = __float_as_uint(q[4 * PA]);
            mma8(acc[0][fn][0], acc[0][fn][1], acc[0][fn][2], acc[0][fn][3],
                 a[0][0], a[0][1], a[0][2], a[0][3], b0, b1);
            mma8(acc[1][fn][0], acc[1][fn][1], acc[1][fn][2], acc[1][fn][3],
                 a[1][0], a[1][1], a[1][2], a[1][3], b0, b1);
        }
    }
}

// Issue one (A,B) k-chunk into stage `buf` via cp.async. Per thread: 8x16B.
#define ISSUE_TILE(buf, k0)                                                   \
    {                                                                         \
        _Pragma("unroll") for (int j = 0; j < 4; j++) {                       \
            cpa16(aAddr[buf] + sdst + j * (8 * PA * 4),                       \
                  aS + (size_t)((k0) + 8 * j) * RSA);                         \
            cpa16(bAddr[buf] + sdst + j * (8 * PA * 4),                       \
                  bS + (size_t)((k0) + 8 * j) * RSB);                         \
        }                                                                     \
        CP_COMMIT();                                                          \
    }

// 3-stage mainloop body (one __syncthreads per chunk)
#define PIPE_LOOP(NCH)                                                        \
    ISSUE_TILE(0, 0);                                                         \
    ISSUE_TILE(1, BK);                                                        \
    for (int cc = 0; cc < (NCH); cc++) {                                      \
        const int cur = cc % NSTAGE;                                          \
        if (cc == (NCH) - 1) { CP_WAIT(0); } else { CP_WAIT(1); }             \
        __syncthreads();                                                      \
        if (cc + 2 < (NCH)) ISSUE_TILE((cc + 2) % NSTAGE, (cc + 2) * BK);     \
        mma_tile(sm + cur * ASZ, sm + (NSTAGE + cur) * ASZ, acc, mw, nw, c, g);\
    }

// ---------------- prep: fused tf32 rounding of all 5 operand tensors ----------------
#define NX4 (BATCH * NHID * LEN / 4)   // 262144
#define NW4 (NHID * DQKV / 4)          // 32768
#define NO4 (DQKV * DOUT / 4)          // 262144
#define NT4 (NX4 + 3 * NW4 + NO4)      // 622592

__global__ __launch_bounds__(256) void cvt_all(
    const float4* __restrict__ x,  const float4* __restrict__ wq,
    const float4* __restrict__ wk, const float4* __restrict__ wv,
    const float4* __restrict__ wo,
    float4* __restrict__ dx,  float4* __restrict__ dwq,
    float4* __restrict__ dwk, float4* __restrict__ dwv,
    float4* __restrict__ dwo)
{
    int i = blockIdx.x * 256 + threadIdx.x;
    if (i >= NT4) return;
    const float4* s;
    float4* d;
    if (i < NX4)                       { s = x  + i;  d = dx  + i; }
    else if (i < NX4 + NW4)            { s = wq + (i - NX4);             d = dwq + (i - NX4); }
    else if (i < NX4 + 2 * NW4)        { s = wk + (i - NX4 - NW4);       d = dwk + (i - NX4 - NW4); }
    else if (i < NX4 + 3 * NW4)        { s = wv + (i - NX4 - 2 * NW4);   d = dwv + (i - NX4 - 2 * NW4); }
    else                               { s = wo + (i - NX4 - 3 * NW4);   d = dwo + (i - NX4 - 3 * NW4); }
    float4 v = *s;
    *(uint4*)d = make_uint4(tf32r(v.x), tf32r(v.y), tf32r(v.z), tf32r(v.w));
}

// ---------------- Kernel 1: QKV projection ----------------
// C[16384 x 1536] = A[16384 x 256] @ W[256 x 512] (x3); A[m][k] = g_x[b][k][l]
__global__ __launch_bounds__(256, 2) void qkv_mma(
    const float* __restrict__ bq, const float* __restrict__ bk,
    const float* __restrict__ bv)
{
    extern __shared__ float sm[];
    const int tid = threadIdx.x, lane = tid & 31, wid = tid >> 5;
    const int c = lane & 3, g = lane >> 2;
    const int mw = (wid & 3) * 32, nw = (wid >> 2) * 64;

    const int m0 = blockIdx.x * BM;
    const int bb = m0 >> 11;
    const int l0 = m0 & (LEN - 1);
    const int yy = blockIdx.y;               // 0..11
    const int mat = yy >> 2;                 // 0=q 1=k 2=v
    const int n0 = (yy & 3) * BN;

    const float* W    = (mat == 0) ? g_wq : (mat == 1) ? g_wk : g_wv;
    const float* bias = (mat == 0) ? bq : (mat == 1) ? bk : bv;

    const size_t RSA = LEN, RSB = DQKV;
    const int kk0 = tid >> 5, m4s = (tid & 31) * 4;
    const uint32_t sbase = smem_u32(sm);
    const uint32_t sdst = (uint32_t)(kk0 * PA + m4s) * 4;
    uint32_t aAddr[NSTAGE], bAddr[NSTAGE];
#pragma unroll
    for (int i = 0; i < NSTAGE; i++) {
        aAddr[i] = sbase + i * ASZ * 4;
        bAddr[i] = sbase + (NSTAGE + i) * ASZ * 4;
    }
    const float* aS = g_x + (size_t)bb * NHID * LEN + l0 + (size_t)kk0 * RSA + m4s;
    const float* bS = W + n0 + (size_t)kk0 * RSB + m4s;

    float acc[2][8][4];
#pragma unroll
    for (int i = 0; i < 2; i++)
#pragma unroll
        for (int j = 0; j < 8; j++)
#pragma unroll
            for (int r = 0; r < 4; r++) acc[i][j][r] = 0.f;

    PIPE_LOOP(NHID / BK);   // 8 chunks

    // Epilogue: direct float2 stores
#pragma unroll
    for (int fm = 0; fm < 2; fm++)
#pragma unroll
        for (int fn = 0; fn < 8; fn++) {
            int m = m0 + mw + fm * 16 + g;
            int n = nw + fn * 8 + c * 2;
            float bx = __ldg(bias + n0 + n), by = __ldg(bias + n0 + n + 1);
            float* p = g_qkv + (size_t)m * 1536 + mat * 512 + n0 + n;
            *(float2*)p = make_float2(acc[fm][fn][0] + bx, acc[fm][fn][1] + by);
            *(float2*)(p + (size_t)8 * 1536) =
                make_float2(acc[fm][fn][2] + bx, acc[fm][fn][3] + by);
        }
}

// ---------------- Kernel 2: window-3 attention, transposed+rounded output ----------------
__global__ __launch_bounds__(256) void attn_t()
{
    __shared__ float att_s[32 * 66];   // [li][d] pitch 66
    const int tid = threadIdx.x, warp = tid >> 5, lane = tid & 31;
    const int bid = blockIdx.x;
    const int b = bid >> 9;
    const int head = (bid >> 6) & 7;
    const int l0 = (bid & 63) * 32;

#pragma unroll
    for (int i = 0; i < 4; i++) {
        const int li = warp * 4 + i;
        const int l = l0 + li;
        const size_t mrow = (size_t)b * LEN + l;
        const float* base = g_qkv + mrow * 1536 + head * HDIM + lane * 2;
        const float2 qv = *(const float2*)base;

        float  s[3];
        float2 vv[3];
#pragma unroll
        for (int w = 0; w < 3; w++) {
            int lw = l + w - 1;
            bool ok = (unsigned)lw < (unsigned)LEN;
            float2 kv = make_float2(0.f, 0.f);
            vv[w] = make_float2(0.f, 0.f);
            if (ok) {
                const float* pw = base + (size_t)(w - 1) * 1536;
                kv    = *(const float2*)(pw + 512);
                vv[w] = *(const float2*)(pw + 1024);
            }
            float p = qv.x * kv.x + qv.y * kv.y;
            p += __shfl_xor_sync(0xffffffffu, p, 16);
            p += __shfl_xor_sync(0xffffffffu, p, 8);
            p += __shfl_xor_sync(0xffffffffu, p, 4);
            p += __shfl_xor_sync(0xffffffffu, p, 2);
            p += __shfl_xor_sync(0xffffffffu, p, 1);
            s[w] = p * 0.125f;  // 1/sqrt(64)
        }

        float mx = fmaxf(s[0], fmaxf(s[1], s[2]));
        float e0 = expf(s[0] - mx), e1 = expf(s[1] - mx), e2 = expf(s[2] - mx);
        float inv = 1.0f / (e0 + e1 + e2);
        float ax = (e0 * vv[0].x + e1 * vv[1].x + e2 * vv[2].x) * inv;
        float ay = (e0 * vv[0].y + e1 * vv[1].y + e2 * vv[2].y) * inv;
        *(float2*)&att_s[li * 66 + lane * 2] = make_float2(ax, ay);
    }
    __syncthreads();

    // write g_att_t[(head*64+d)][b*2048 + l0 + 0..31], float4 along l, tf32-rounded
#pragma unroll
    for (int i = 0; i < 2; i++) {
        int f = tid + i * 256;
        int d = f >> 3;                 // 0..63
        int q4 = (f & 7) * 4;           // 0..28
        uint4 v = make_uint4(tf32r(att_s[(q4 + 0) * 66 + d]),
                             tf32r(att_s[(q4 + 1) * 66 + d]),
                             tf32r(att_s[(q4 + 2) * 66 + d]),
                             tf32r(att_s[(q4 + 3) * 66 + d]));
        *(uint4*)(g_att_t + ((size_t)(head * HDIM + d)) * MTOT
                  + (size_t)b * LEN + l0 + q4) = v;
    }
}

// ---------------- Kernel 3: output projection + transposed write ----------------
// out[b][o][l] = att[m][512] @ Wo[512][2048] + bo;  A from g_att_t [k][m]
__global__ __launch_bounds__(256, 2) void out_mma(
    const float* __restrict__ bo, float* __restrict__ out)
{
    extern __shared__ float sm[];
    const int tid = threadIdx.x, lane = tid & 31, wid = tid >> 5;
    const int c = lane & 3, g = lane >> 2;
    const int mw = (wid & 3) * 32, nw = (wid >> 2) * 64;

    const int m0 = blockIdx.x * BM;
    const int bb = m0 >> 11;
    const int l0 = m0 & (LEN - 1);
    const int n0 = blockIdx.y * BN;

    const size_t RSA = MTOT, RSB = DOUT;
    const int kk0 = tid >> 5, m4s = (tid & 31) * 4;
    const uint32_t sbase = smem_u32(sm);
    const uint32_t sdst = (uint32_t)(kk0 * PA + m4s) * 4;
    uint32_t aAddr[NSTAGE], bAddr[NSTAGE];
#pragma unroll
    for (int i = 0; i < NSTAGE; i++) {
        aAddr[i] = sbase + i * ASZ * 4;
        bAddr[i] = sbase + (NSTAGE + i) * ASZ * 4;
    }
    const float* aS = g_att_t + m0 + (size_t)kk0 * RSA + m4s;
    const float* bS = g_wo + n0 + (size_t)kk0 * RSB + m4s;

    float acc[2][8][4];
#pragma unroll
    for (int i = 0; i < 2; i++)
#pragma unroll
        for (int j = 0; j < 8; j++)
#pragma unroll
            for (int r = 0; r < 4; r++) acc[i][j][r] = 0.f;

    PIPE_LOOP(DQKV / BK);   // 16 chunks

    __syncthreads();   // protect stage buffers before epilogue reuse

    // Epilogue: bounce C through smem as [n][m], then 128B stores along l
    float* ep = sm;   // 128*132 floats = 67584 B <= SMEM_DYN
#pragma unroll
    for (int fm = 0; fm < 2; fm++)
#pragma unroll
        for (int fn = 0; fn < 8; fn++) {
            int nrel = nw + fn * 8 + c * 2;
            int mrel = mw + fm * 16 + g;
            ep[nrel * EPP + mrel]           = acc[fm][fn][0];
            ep[(nrel + 1) * EPP + mrel]     = acc[fm][fn][1];
            ep[nrel * EPP + mrel + 8]       = acc[fm][fn][2];
            ep[(nrel + 1) * EPP + mrel + 8] = acc[fm][fn][3];
        }
    __syncthreads();
#pragma unroll
    for (int i = 0; i < 16; i++) {
        int f = tid + i * 256;
        int nr = f >> 5;                // 0..127
        int m4 = (f & 31) * 4;          // 0..124
        float4 v = *(float4*)&ep[nr * EPP + m4];
        float bj = __ldg(bo + n0 + nr);
        v.x += bj; v.y += bj; v.z += bj; v.w += bj;
        *(float4*)(out + ((size_t)(bb * DOUT + n0 + nr)) * LEN + l0 + m4) = v;
    }
}

// ---------------- launch ----------------
extern "C" void kernel_launch(void* const* d_in, const int* in_sizes, int n_in,
                              void* d_out, int out_size)
{
    const float* x  = (const float*)d_in[0];
    const float* Wq = (const float*)d_in[1];
    const float* bq = (const float*)d_in[2];
    const float* Wk = (const float*)d_in[3];
    const float* bk = (const float*)d_in[4];
    const float* Wv = (const float*)d_in[5];
    const float* bv = (const float*)d_in[6];
    const float* Wo = (const float*)d_in[7];
    const float* bo = (const float*)d_in[8];
    float* out = (float*)d_out;

    cudaFuncSetAttribute(qkv_mma, cudaFuncAttributeMaxDynamicSharedMemorySize, SMEM_DYN);
    cudaFuncSetAttribute(out_mma, cudaFuncAttributeMaxDynamicSharedMemorySize, SMEM_DYN);

    float* gx;  cudaGetSymbolAddress((void**)&gx,  g_x);
    float* gwq; cudaGetSymbolAddress((void**)&gwq, g_wq);
    float* gwk; cudaGetSymbolAddress((void**)&gwk, g_wk);
    float* gwv; cudaGetSymbolAddress((void**)&gwv, g_wv);
    float* gwo; cudaGetSymbolAddress((void**)&gwo, g_wo);

    cvt_all<<<(NT4 + 255) / 256, 256>>>(
        (const float4*)x, (const float4*)Wq, (const float4*)Wk,
        (const float4*)Wv, (const float4*)Wo,
        (float4*)gx, (float4*)gwq, (float4*)gwk, (float4*)gwv, (float4*)gwo);

    qkv_mma<<<dim3(MTOT / BM, 12), 256, SMEM_DYN>>>(bq, bk, bv);
    attn_t<<<BATCH * NHEAD * (LEN / 32), 256>>>();
    out_mma<<<dim3(MTOT / BM, DOUT / BN), 256, SMEM_DYN>>>(bo, out);
}

// round 6
// speedup vs baseline: 3.2697x; 1.0448x over previous
#include <cuda_runtime.h>
#include <cstdint>

// ---------------- problem constants ----------------
#define BATCH 8
#define NHID 256
#define LEN 2048
#define NHEAD 8
#define HDIM 64
#define DQKV 512
#define DOUT 2048
#define MTOT (BATCH * LEN)   // 16384

// ---------------- qkv GEMM tiling (unchanged from R5) ----------------
#define BM 128
#define BN 128
#define BK 32
#define PA 136
#define ASZ (BK * PA)
#define NSTAGE 3
#define SMEM_DYN (2 * NSTAGE * ASZ * 4)   // 104448 bytes

// ---------------- out GEMM tiling (new: 4 CTAs/SM) ----------------
#define OM 64                 // m tile
#define ON 128                // n tile
#define PAO 72                // A smem pitch (floats) for 64-m rows; 8c banking
#define AOSZ (BK * PAO)       // 2304 floats
#define BOSZ (BK * PA)        // 4352 floats
#define EPPO 68               // epilogue bounce pitch
#define OSM_DYN ((2 * (AOSZ + BOSZ)) * 4)   // 53248 bytes; epilogue needs 34816

// Scratch (allocation-free: __device__ globals). All tf32-pre-rounded operands.
__device__ float g_x[(size_t)BATCH * NHID * LEN];
__device__ float g_wq[NHID * DQKV];
__device__ float g_wk[NHID * DQKV];
__device__ float g_wv[NHID * DQKV];
__device__ float g_wo[DQKV * DOUT];
__device__ float g_qkv[(size_t)MTOT * 1536];
__device__ float g_att_t[(size_t)DQKV * MTOT];

// ---------------- helpers ----------------
__device__ __forceinline__ uint32_t tf32r(float f) {
    uint32_t u;
    asm("cvt.rna.tf32.f32 %0, %1;" : "=r"(u) : "f"(f));
    return u;
}
__device__ __forceinline__ uint32_t smem_u32(const void* p) {
    uint32_t a;
    asm("{ .reg .u64 t; cvta.to.shared.u64 t, %1; cvt.u32.u64 %0, t; }" : "=r"(a) : "l"(p));
    return a;
}
__device__ __forceinline__ void cpa16(uint32_t dst, const void* src) {
    asm volatile("cp.async.cg.shared.global [%0], [%1], 16;" :: "r"(dst), "l"(src));
}
#define CP_COMMIT() asm volatile("cp.async.commit_group;" ::: "memory")
#define CP_WAIT(n)  asm volatile("cp.async.wait_group %0;" :: "n"(n) : "memory")

__device__ __forceinline__ void mma8(float& d0, float& d1, float& d2, float& d3,
                                     uint32_t a0, uint32_t a1, uint32_t a2, uint32_t a3,
                                     uint32_t b0, uint32_t b1) {
    asm volatile(
        "mma.sync.aligned.m16n8k8.row.col.f32.tf32.tf32.f32 "
        "{%0,%1,%2,%3}, {%4,%5,%6,%7}, {%8,%9}, {%0,%1,%2,%3};"
        : "+f"(d0), "+f"(d1), "+f"(d2), "+f"(d3)
        : "r"(a0), "r"(a1), "r"(a2), "r"(a3), "r"(b0), "r"(b1));
}

// mma over one staged (A,B) tile pair; A pitch parameterized. acc[fm][fn][r]
template <int APITCH>
__device__ __forceinline__ void mma_tile(const float* __restrict__ Ab,
                                         const float* __restrict__ Bb,
                                         float acc[2][8][4], int mw, int nw,
                                         int c, int g) {
#pragma unroll
    for (int ks = 0; ks < BK; ks += 8) {
        uint32_t a[2][4];
#pragma unroll
        for (int fm = 0; fm < 2; fm++) {
            const float* p = Ab + (ks + c) * APITCH + mw + fm * 16 + g;
            a[fm][0] = __float_as_uint(p[0]);
            a[fm][1] = __float_as_uint(p[8]);
            a[fm][2] = __float_as_uint(p[4 * APITCH]);
            a[fm][3] = __float_as_uint(p[4 * APITCH + 8]);
        }
#pragma unroll
        for (int fn = 0; fn < 8; fn++) {
            const float* q = Bb + (ks + c) * PA + nw + fn * 8 + g;
            uint32_t b0 = __float_as_uint(q[0]);
            uint32_t b1 = __float_as_uint(q[4 * PA]);
            mma8(acc[0][fn][0], acc[0][fn][1], acc[0][fn][2], acc[0][fn][3],
                 a[0][0], a[0][1], a[0][2], a[0][3], b0, b1);
            mma8(acc[1][fn][0], acc[1][fn][1], acc[1][fn][2], acc[1][fn][3],
                 a[1][0], a[1][1], a[1][2], a[1][3], b0, b1);
        }
    }
}

// ---------------- prep: fused tf32 rounding ----------------
#define NX4 (BATCH * NHID * LEN / 4)
#define NW4 (NHID * DQKV / 4)
#define NO4 (DQKV * DOUT / 4)
#define NT4 (NX4 + 3 * NW4 + NO4)

__global__ __launch_bounds__(256) void cvt_all(
    const float4* __restrict__ x,  const float4* __restrict__ wq,
    const float4* __restrict__ wk, const float4* __restrict__ wv,
    const float4* __restrict__ wo,
    float4* __restrict__ dx,  float4* __restrict__ dwq,
    float4* __restrict__ dwk, float4* __restrict__ dwv,
    float4* __restrict__ dwo)
{
    int i = blockIdx.x * 256 + threadIdx.x;
    if (i >= NT4) return;
    const float4* s;
    float4* d;
    if (i < NX4)                { s = x  + i;  d = dx  + i; }
    else if (i < NX4 + NW4)     { s = wq + (i - NX4);           d = dwq + (i - NX4); }
    else if (i < NX4 + 2 * NW4) { s = wk + (i - NX4 - NW4);     d = dwk + (i - NX4 - NW4); }
    else if (i < NX4 + 3 * NW4) { s = wv + (i - NX4 - 2 * NW4); d = dwv + (i - NX4 - 2 * NW4); }
    else                        { s = wo + (i - NX4 - 3 * NW4); d = dwo + (i - NX4 - 3 * NW4); }
    float4 v = *s;
    *(uint4*)d = make_uint4(tf32r(v.x), tf32r(v.y), tf32r(v.z), tf32r(v.w));
}

// ---------------- Kernel 1: QKV projection (R5 structure, unchanged) ----------------
#define ISSUE_TILE(buf, k0)                                                   \
    {                                                                         \
        _Pragma("unroll") for (int j = 0; j < 4; j++) {                       \
            cpa16(aAddr[buf] + sdst + j * (8 * PA * 4),                       \
                  aS + (size_t)((k0) + 8 * j) * RSA);                         \
            cpa16(bAddr[buf] + sdst + j * (8 * PA * 4),                       \
                  bS + (size_t)((k0) + 8 * j) * RSB);                         \
        }                                                                     \
        CP_COMMIT();                                                          \
    }

__global__ __launch_bounds__(256, 2) void qkv_mma(
    const float* __restrict__ bq, const float* __restrict__ bk,
    const float* __restrict__ bv)
{
    extern __shared__ float sm[];
    const int tid = threadIdx.x, lane = tid & 31, wid = tid >> 5;
    const int c = lane & 3, g = lane >> 2;
    const int mw = (wid & 3) * 32, nw = (wid >> 2) * 64;

    const int m0 = blockIdx.x * BM;
    const int bb = m0 >> 11;
    const int l0 = m0 & (LEN - 1);
    const int yy = blockIdx.y;
    const int mat = yy >> 2;
    const int n0 = (yy & 3) * BN;

    const float* W    = (mat == 0) ? g_wq : (mat == 1) ? g_wk : g_wv;
    const float* bias = (mat == 0) ? bq : (mat == 1) ? bk : bv;

    const size_t RSA = LEN, RSB = DQKV;
    const int kk0 = tid >> 5, m4s = (tid & 31) * 4;
    const uint32_t sbase = smem_u32(sm);
    const uint32_t sdst = (uint32_t)(kk0 * PA + m4s) * 4;
    uint32_t aAddr[NSTAGE], bAddr[NSTAGE];
#pragma unroll
    for (int i = 0; i < NSTAGE; i++) {
        aAddr[i] = sbase + i * ASZ * 4;
        bAddr[i] = sbase + (NSTAGE + i) * ASZ * 4;
    }
    const float* aS = g_x + (size_t)bb * NHID * LEN + l0 + (size_t)kk0 * RSA + m4s;
    const float* bS = W + n0 + (size_t)kk0 * RSB + m4s;

    float acc[2][8][4];
#pragma unroll
    for (int i = 0; i < 2; i++)
#pragma unroll
        for (int j = 0; j < 8; j++)
#pragma unroll
            for (int r = 0; r < 4; r++) acc[i][j][r] = 0.f;

    const int NCH = NHID / BK;  // 8
    ISSUE_TILE(0, 0);
    ISSUE_TILE(1, BK);
    for (int cc = 0; cc < NCH; cc++) {
        const int cur = cc % NSTAGE;
        if (cc == NCH - 1) { CP_WAIT(0); } else { CP_WAIT(1); }
        __syncthreads();
        if (cc + 2 < NCH) ISSUE_TILE((cc + 2) % NSTAGE, (cc + 2) * BK);
        mma_tile<PA>(sm + cur * ASZ, sm + (NSTAGE + cur) * ASZ, acc, mw, nw, c, g);
    }

#pragma unroll
    for (int fm = 0; fm < 2; fm++)
#pragma unroll
        for (int fn = 0; fn < 8; fn++) {
            int m = m0 + mw + fm * 16 + g;
            int n = nw + fn * 8 + c * 2;
            float bx = __ldg(bias + n0 + n), by = __ldg(bias + n0 + n + 1);
            float* p = g_qkv + (size_t)m * 1536 + mat * 512 + n0 + n;
            *(float2*)p = make_float2(acc[fm][fn][0] + bx, acc[fm][fn][1] + by);
            *(float2*)(p + (size_t)8 * 1536) =
                make_float2(acc[fm][fn][2] + bx, acc[fm][fn][3] + by);
        }
}

// ---------------- Kernel 2: window-3 attention (unchanged) ----------------
__global__ __launch_bounds__(256) void attn_t()
{
    __shared__ float att_s[32 * 66];
    const int tid = threadIdx.x, warp = tid >> 5, lane = tid & 31;
    const int bid = blockIdx.x;
    const int b = bid >> 9;
    const int head = (bid >> 6) & 7;
    const int l0 = (bid & 63) * 32;

#pragma unroll
    for (int i = 0; i < 4; i++) {
        const int li = warp * 4 + i;
        const int l = l0 + li;
        const size_t mrow = (size_t)b * LEN + l;
        const float* base = g_qkv + mrow * 1536 + head * HDIM + lane * 2;
        const float2 qv = *(const float2*)base;

        float  s[3];
        float2 vv[3];
#pragma unroll
        for (int w = 0; w < 3; w++) {
            int lw = l + w - 1;
            bool ok = (unsigned)lw < (unsigned)LEN;
            float2 kv = make_float2(0.f, 0.f);
            vv[w] = make_float2(0.f, 0.f);
            if (ok) {
                const float* pw = base + (size_t)(w - 1) * 1536;
                kv    = *(const float2*)(pw + 512);
                vv[w] = *(const float2*)(pw + 1024);
            }
            float p = qv.x * kv.x + qv.y * kv.y;
            p += __shfl_xor_sync(0xffffffffu, p, 16);
            p += __shfl_xor_sync(0xffffffffu, p, 8);
            p += __shfl_xor_sync(0xffffffffu, p, 4);
            p += __shfl_xor_sync(0xffffffffu, p, 2);
            p += __shfl_xor_sync(0xffffffffu, p, 1);
            s[w] = p * 0.125f;
        }

        float mx = fmaxf(s[0], fmaxf(s[1], s[2]));
        float e0 = expf(s[0] - mx), e1 = expf(s[1] - mx), e2 = expf(s[2] - mx);
        float inv = 1.0f / (e0 + e1 + e2);
        float ax = (e0 * vv[0].x + e1 * vv[1].x + e2 * vv[2].x) * inv;
        float ay = (e0 * vv[0].y + e1 * vv[1].y + e2 * vv[2].y) * inv;
        *(float2*)&att_s[li * 66 + lane * 2] = make_float2(ax, ay);
    }
    __syncthreads();

#pragma unroll
    for (int i = 0; i < 2; i++) {
        int f = tid + i * 256;
        int d = f >> 3;
        int q4 = (f & 7) * 4;
        uint4 v = make_uint4(tf32r(att_s[(q4 + 0) * 66 + d]),
                             tf32r(att_s[(q4 + 1) * 66 + d]),
                             tf32r(att_s[(q4 + 2) * 66 + d]),
                             tf32r(att_s[(q4 + 3) * 66 + d]));
        *(uint4*)(g_att_t + ((size_t)(head * HDIM + d)) * MTOT
                  + (size_t)b * LEN + l0 + q4) = v;
    }
}

// ---------------- Kernel 3: output projection — 128 threads, 64x128 tile, 4 CTAs/SM ----------------
__global__ __launch_bounds__(128, 4) void out_mma(
    const float* __restrict__ bo, float* __restrict__ out)
{
    extern __shared__ float sm[];
    // layout: A0 [AOSZ], A1 [AOSZ], B0 [BOSZ], B1 [BOSZ]
    const int tid = threadIdx.x, lane = tid & 31, wid = tid >> 5;
    const int c = lane & 3, g = lane >> 2;
    const int mw = (wid & 1) * 32, nw = (wid >> 1) * 64;

    const int m0 = blockIdx.x * OM;        // 64-aligned, never crosses batch
    const int bb = m0 >> 11;
    const int l0 = m0 & (LEN - 1);
    const int n0 = blockIdx.y * ON;

    const size_t RSA = MTOT, RSB = DOUT;
    const uint32_t sbase = smem_u32(sm);
    // A staging: f = tid + j*128 (j<4): kk = f>>4, m4 = (f&15)*4
    const int akk = tid >> 4, am4 = (tid & 15) * 4;
    const uint32_t adst = (uint32_t)(akk * PAO + am4) * 4;
    const float* aS = g_att_t + m0 + (size_t)akk * RSA + am4;
    // B staging: f = tid + j*128 (j<8): kk = f>>5, n4 = (f&31)*4
    const int bkk = tid >> 5, bn4 = (tid & 31) * 4;
    const uint32_t bdst = (uint32_t)(bkk * PA + bn4) * 4;
    const float* bS = g_wo + n0 + (size_t)bkk * RSB + bn4;

    const uint32_t aA[2] = {sbase, sbase + AOSZ * 4};
    const uint32_t bA[2] = {sbase + 2 * AOSZ * 4, sbase + (2 * AOSZ + BOSZ) * 4};

#define O_ISSUE(buf, k0)                                                      \
    {                                                                         \
        _Pragma("unroll") for (int j = 0; j < 4; j++)                         \
            cpa16(aA[buf] + adst + j * (8 * PAO * 4),                         \
                  aS + (size_t)((k0) + 8 * j) * RSA);                         \
        _Pragma("unroll") for (int j = 0; j < 8; j++)                         \
            cpa16(bA[buf] + bdst + j * (4 * PA * 4),                          \
                  bS + (size_t)((k0) + 4 * j) * RSB);                         \
        CP_COMMIT();                                                          \
    }

    float acc[2][8][4];
#pragma unroll
    for (int i = 0; i < 2; i++)
#pragma unroll
        for (int j = 0; j < 8; j++)
#pragma unroll
            for (int r = 0; r < 4; r++) acc[i][j][r] = 0.f;

    const int NCH = DQKV / BK;  // 16
    O_ISSUE(0, 0);
    for (int cc = 0; cc < NCH; cc++) {
        const int cur = cc & 1;
        if (cc + 1 < NCH) { O_ISSUE(cur ^ 1, (cc + 1) * BK); CP_WAIT(1); }
        else              { CP_WAIT(0); }
        __syncthreads();
        mma_tile<PAO>((const float*)(sm + cur * AOSZ),
                      (const float*)(sm + 2 * AOSZ + cur * BOSZ),
                      acc, mw, nw, c, g);
        __syncthreads();
    }

    // Epilogue: bounce C through smem as [n][m] (pitch 68), then 256B rows along l
    float* ep = sm;   // 128*68*4 = 34816 B <= 53248
#pragma unroll
    for (int fm = 0; fm < 2; fm++)
#pragma unroll
        for (int fn = 0; fn < 8; fn++) {
            int nrel = nw + fn * 8 + c * 2;
            int mrel = mw + fm * 16 + g;
            ep[nrel * EPPO + mrel]           = acc[fm][fn][0];
            ep[(nrel + 1) * EPPO + mrel]     = acc[fm][fn][1];
            ep[nrel * EPPO + mrel + 8]       = acc[fm][fn][2];
            ep[(nrel + 1) * EPPO + mrel + 8] = acc[fm][fn][3];
        }
    __syncthreads();
#pragma unroll
    for (int i = 0; i < 16; i++) {
        int f = tid + i * 128;
        int nr = f >> 4;                // 0..127
        int m4 = (f & 15) * 4;          // 0..60
        float4 v = *(float4*)&ep[nr * EPPO + m4];
        float bj = __ldg(bo + n0 + nr);
        v.x += bj; v.y += bj; v.z += bj; v.w += bj;
        *(float4*)(out + ((size_t)(bb * DOUT + n0 + nr)) * LEN + l0 + m4) = v;
    }
#undef O_ISSUE
}

// ---------------- launch ----------------
extern "C" void kernel_launch(void* const* d_in, const int* in_sizes, int n_in,
                              void* d_out, int out_size)
{
    const float* x  = (const float*)d_in[0];
    const float* Wq = (const float*)d_in[1];
    const float* bq = (const float*)d_in[2];
    const float* Wk = (const float*)d_in[3];
    const float* bk = (const float*)d_in[4];
    const float* Wv = (const float*)d_in[5];
    const float* bv = (const float*)d_in[6];
    const float* Wo = (const float*)d_in[7];
    const float* bo = (const float*)d_in[8];
    float* out = (float*)d_out;

    cudaFuncSetAttribute(qkv_mma, cudaFuncAttributeMaxDynamicSharedMemorySize, SMEM_DYN);
    cudaFuncSetAttribute(out_mma, cudaFuncAttributeMaxDynamicSharedMemorySize, OSM_DYN);

    float* gx;  cudaGetSymbolAddress((void**)&gx,  g_x);
    float* gwq; cudaGetSymbolAddress((void**)&gwq, g_wq);
    float* gwk; cudaGetSymbolAddress((void**)&gwk, g_wk);
    float* gwv; cudaGetSymbolAddress((void**)&gwv, g_wv);
    float* gwo; cudaGetSymbolAddress((void**)&gwo, g_wo);

    cvt_all<<<(NT4 + 255) / 256, 256>>>(
        (const float4*)x, (const float4*)Wq, (const float4*)Wk,
        (const float4*)Wv, (const float4*)Wo,
        (float4*)gx, (float4*)gwq, (float4*)gwk, (float4*)gwv, (float4*)gwo);

    qkv_mma<<<dim3(MTOT / BM, 12), 256, SMEM_DYN>>>(bq, bk, bv);
    attn_t<<<BATCH * NHEAD * (LEN / 32), 256>>>();
    out_mma<<<dim3(MTOT / OM, DOUT / ON), 128, OSM_DYN>>>(bo, out);
}